// round 15
// baseline (speedup 1.0000x reference)
#include <cuda_runtime.h>
#include <cuda_bf16.h>
#include <cuda_fp16.h>
#include <cstdint>

#define NN 100000
#define NE 1600000
#define NG 512
#define LDP 136   // padded smem row stride in fp16 elements (272 B)

// ---------------- scratch (device globals) -------------------------------
// Invariants at entry to each run (zero-init at load; k_pool_out restores):
//   g_deg[i] == 0, g_bsum[b] == 0
__device__ int    g_deg[NN];
__device__ float  g_dis[NN];
__device__ float4 g_u4[NN];
__device__ __align__(16) __half2 g_hh[NN * 64];   // fp16 node features
__device__ __align__(16) __half2 g_uh[NN * 64];   // fp16 projected features
__device__ int    g_rowstart[NN];
__device__ unsigned short g_rank[NE];             // within-row rank per edge
__device__ int    g_col[NE];
__device__ int    g_bsum[512];
__device__ __align__(16) unsigned short g_B[2][16384];

// ---------------- mma helper (f16 inputs, f32 accum) ---------------------
__device__ __forceinline__ void mma_f16(float& d0, float& d1, float& d2, float& d3,
                                        uint32_t a0, uint32_t a1, uint32_t a2, uint32_t a3,
                                        uint32_t b0, uint32_t b1) {
    asm volatile(
        "mma.sync.aligned.m16n8k16.row.col.f32.f16.f16.f32 "
        "{%0,%1,%2,%3}, {%4,%5,%6,%7}, {%8,%9}, {%0,%1,%2,%3};"
        : "+f"(d0), "+f"(d1), "+f"(d2), "+f"(d3)
        : "r"(a0), "r"(a1), "r"(a2), "r"(a3), "r"(b0), "r"(b1));
}

// ---------------- front: W prep + degree count + edge ranks --------------
__global__ void k_front(const int* __restrict__ dst, int E,
                        const float* __restrict__ W2, const float* __restrict__ W3) {
    int gid = blockIdx.x * blockDim.x + threadIdx.x;
    if (gid < 32768) {
        int which = gid >> 14;
        int idx = gid & 16383;
        int k  = idx >> 7;
        int nn = idx & 127;
        const float* W = which ? W3 : W2;
        g_B[which][nn * 128 + k] = __half_as_ushort(__float2half_rn(W[k * 128 + nn]));
    }
    int wid  = gid >> 5;
    int lane = gid & 31;
    int base = wid * 128 + lane;
    int d0 = -1, d1 = -1, d2 = -1, d3 = -1;
    if (base       < E) d0 = dst[base];
    if (base + 32  < E) d1 = dst[base + 32];
    if (base + 64  < E) d2 = dst[base + 64];
    if (base + 96  < E) d3 = dst[base + 96];
    int r0 = 0, r1 = 0, r2 = 0, r3 = 0;
    if (d0 >= 0) r0 = atomicAdd(&g_deg[d0], 1);
    if (d1 >= 0) r1 = atomicAdd(&g_deg[d1], 1);
    if (d2 >= 0) r2 = atomicAdd(&g_deg[d2], 1);
    if (d3 >= 0) r3 = atomicAdd(&g_deg[d3], 1);
    if (d0 >= 0) g_rank[base]      = (unsigned short)r0;
    if (d1 >= 0) g_rank[base + 32] = (unsigned short)r1;
    if (d2 >= 0) g_rank[base + 64] = (unsigned short)r2;
    if (d3 >= 0) g_rank[base + 96] = (unsigned short)r3;
}

// ---------------- merged scan (decoupled lookback) + dis -----------------
__global__ void k_scan(int n) {
    __shared__ int s[256];
    __shared__ int partials[256];
    int t = threadIdx.x;
    int bid = blockIdx.x;
    int i = bid * 256 + t;
    int raw = (i < n) ? g_deg[i] : 0;
    if (i < n) g_dis[i] = rsqrtf((float)(raw + 1));
    s[t] = raw;
    __syncthreads();
#pragma unroll
    for (int off = 1; off < 256; off <<= 1) {
        int x = (t >= off) ? s[t - off] : 0;
        __syncthreads();
        s[t] += x;
        __syncthreads();
    }
    if (t == 255) atomicExch(&g_bsum[bid], s[255] + 1);
    int partial = 0;
    for (int b = t; b < bid; b += 256) {
        int v;
        do { v = atomicAdd(&g_bsum[b], 0); } while (v == 0);
        partial += v - 1;
    }
    partials[t] = partial;
    __syncthreads();
#pragma unroll
    for (int off = 128; off > 0; off >>= 1) {
        if (t < off) partials[t] += partials[t + off];
        __syncthreads();
    }
    int base = partials[0];
    if (i < n) g_rowstart[i] = base + s[t] - raw;
}

// ---------------- fused: CSR fill (rank-based, no atomics) + dense1 ------
__global__ void k_fill_dense(const int* __restrict__ src,
                             const int* __restrict__ dst, int E,
                             const float* __restrict__ x,
                             const float* __restrict__ W,
                             const float* __restrict__ b, int n) {
    int gid = blockIdx.x * blockDim.x + threadIdx.x;
    int wid  = gid >> 5;
    int lane = gid & 31;
    int base = wid * 128 + lane;
    int d0 = -1, d1 = -1, d2 = -1, d3 = -1;
    int s0 = 0, s1 = 0, s2 = 0, s3 = 0;
    int r0 = 0, r1 = 0, r2 = 0, r3 = 0;
    if (base       < E) { d0 = dst[base];      s0 = src[base];      r0 = g_rank[base]; }
    if (base + 32  < E) { d1 = dst[base + 32]; s1 = src[base + 32]; r1 = g_rank[base + 32]; }
    if (base + 64  < E) { d2 = dst[base + 64]; s2 = src[base + 64]; r2 = g_rank[base + 64]; }
    if (base + 96  < E) { d3 = dst[base + 96]; s3 = src[base + 96]; r3 = g_rank[base + 96]; }
    int p0 = 0, p1 = 0, p2 = 0, p3 = 0;
    if (d0 >= 0) p0 = g_rowstart[d0] + r0;
    if (d1 >= 0) p1 = g_rowstart[d1] + r1;
    if (d2 >= 0) p2 = g_rowstart[d2] + r2;
    if (d3 >= 0) p3 = g_rowstart[d3] + r3;
    if (d0 >= 0) g_col[p0] = s0;
    if (d1 >= 0) g_col[p1] = s1;
    if (d2 >= 0) g_col[p2] = s2;
    if (d3 >= 0) g_col[p3] = s3;

    if (gid < n) {
        float4 xi = ((const float4*)x)[gid];
        float d = g_dis[gid];
        float4 o;
        o.x = fmaxf(b[0] + xi.x * W[0] + xi.y * W[4] + xi.z * W[8]  + xi.w * W[12], 0.f) * d;
        o.y = fmaxf(b[1] + xi.x * W[1] + xi.y * W[5] + xi.z * W[9]  + xi.w * W[13], 0.f) * d;
        o.z = fmaxf(b[2] + xi.x * W[2] + xi.y * W[6] + xi.z * W[10] + xi.w * W[14], 0.f) * d;
        o.w = fmaxf(b[3] + xi.x * W[3] + xi.y * W[7] + xi.z * W[11] + xi.w * W[15], 0.f) * d;
        g_u4[gid] = o;
    }
}

// ---------------- layer1: 2 threads/node agg + warp projection -----------
// grid: 782 blocks x 256 threads; block handles 128 nodes.
__global__ void k_layer1(const float* __restrict__ Wg1,
                         const float* __restrict__ bg1, int n) {
    __shared__ float4 sagg[256];   // [half][node] = half*128 + li
    int t = threadIdx.x;
    int li   = t & 127;
    int half = t >> 7;
    int i = blockIdx.x * 128 + li;

    // phase 1: two threads split each node's neighbor list (stride 2)
    float4 a0 = make_float4(0.f, 0.f, 0.f, 0.f);
    float4 a1 = make_float4(0.f, 0.f, 0.f, 0.f);
    if (i < n) {
        int start = g_rowstart[i];
        int cnt   = g_deg[i];
        if (half == 0) a0 = g_u4[i];   // self-loop
        int j = half;
        for (; j + 6 < cnt; j += 8) {
            int c0 = g_col[start + j + 0];
            int c1 = g_col[start + j + 2];
            int c2 = g_col[start + j + 4];
            int c3 = g_col[start + j + 6];
            float4 v0 = g_u4[c0];
            float4 v1 = g_u4[c1];
            float4 v2 = g_u4[c2];
            float4 v3 = g_u4[c3];
            a0.x += v0.x; a0.y += v0.y; a0.z += v0.z; a0.w += v0.w;
            a1.x += v1.x; a1.y += v1.y; a1.z += v1.z; a1.w += v1.w;
            a0.x += v2.x; a0.y += v2.y; a0.z += v2.z; a0.w += v2.w;
            a1.x += v3.x; a1.y += v3.y; a1.z += v3.z; a1.w += v3.w;
        }
        for (; j < cnt; j += 2) {
            float4 v = g_u4[g_col[start + j]];
            a0.x += v.x; a0.y += v.y; a0.z += v.z; a0.w += v.w;
        }
    }
    sagg[half * 128 + li] = make_float4(a0.x + a1.x, a0.y + a1.y,
                                        a0.z + a1.z, a0.w + a1.w);
    __syncthreads();

    // phase 2: warp per 16 nodes; weights loaded once per warp
    int w = t >> 5;
    int lane = t & 31;
    int c = lane * 4;
    float4 w0 = *(const float4*)(Wg1 + 0 * 128 + c);
    float4 w1 = *(const float4*)(Wg1 + 1 * 128 + c);
    float4 w2 = *(const float4*)(Wg1 + 2 * 128 + c);
    float4 w3 = *(const float4*)(Wg1 + 3 * 128 + c);
    float4 bb = *(const float4*)(bg1 + c);
    int nd0 = w * 16;
#pragma unroll 4
    for (int k = 0; k < 16; k++) {
        int ln = nd0 + k;
        int gi = blockIdx.x * 128 + ln;
        if (gi >= n) break;
        float4 s0 = sagg[ln];
        float4 s1 = sagg[128 + ln];
        float d = g_dis[gi];
        float ax = d * (s0.x + s1.x), ay = d * (s0.y + s1.y);
        float az = d * (s0.z + s1.z), aw = d * (s0.w + s1.w);
        float ox = fmaxf(bb.x + ax * w0.x + ay * w1.x + az * w2.x + aw * w3.x, 0.f);
        float oy = fmaxf(bb.y + ax * w0.y + ay * w1.y + az * w2.y + aw * w3.y, 0.f);
        float oz = fmaxf(bb.z + ax * w0.z + ay * w1.z + az * w2.z + aw * w3.z, 0.f);
        float ow = fmaxf(bb.w + ax * w0.w + ay * w1.w + az * w2.w + aw * w3.w, 0.f);
        uint2 p;
        *(__half2*)&p.x = __floats2half2_rn(ox, oy);
        *(__half2*)&p.y = __floats2half2_rn(oz, ow);
        ((uint2*)g_hh)[(size_t)gi * 32 + lane] = p;
    }
}

// ---------------- mma.sync GEMM: u16 = fp16(dis * (h16 @ W)) -------------
__global__ void __launch_bounds__(256, 2)
k_gemm_mma(int which, int n) {
    extern __shared__ __align__(16) unsigned short sm[];
    unsigned short* As = sm;
    unsigned short* Bs = sm + 128 * LDP;

    const int tid = threadIdx.x;
    const int m0 = blockIdx.x * 128;

    for (int idx = tid; idx < 2048; idx += 256) {
        int row = idx >> 4;
        int q   = idx & 15;
        int gr = m0 + row;
        if (gr >= n) gr = n - 1;
        uint4 v = ((const uint4*)g_hh)[(size_t)gr * 16 + q];
        *(uint4*)(As + row * LDP + q * 8) = v;
    }
    {
        const uint4* bsrc = (const uint4*)g_B[which];
        for (int i = tid; i < 2048; i += 256) {
            int r = i >> 4;
            int q = i & 15;
            *(uint4*)(Bs + r * LDP + q * 8) = bsrc[i];
        }
    }
    __syncthreads();

    const int w    = tid >> 5;
    const int lane = tid & 31;
    const int mrow = (w >> 1) * 32;
    const int ncol = (w & 1) * 64;
    const int g    = lane >> 2;
    const int tg   = lane & 3;

    float acc[2][8][4];
#pragma unroll
    for (int mt = 0; mt < 2; mt++)
#pragma unroll
        for (int nt = 0; nt < 8; nt++)
#pragma unroll
            for (int c = 0; c < 4; c++) acc[mt][nt][c] = 0.f;

    for (int k0 = 0; k0 < 128; k0 += 16) {
        uint32_t a[2][4];
#pragma unroll
        for (int mt = 0; mt < 2; mt++) {
            const unsigned short* ph = As + (mrow + mt * 16 + g) * LDP + k0 + tg * 2;
            a[mt][0] = *(const uint32_t*)(ph);
            a[mt][1] = *(const uint32_t*)(ph + 8 * LDP);
            a[mt][2] = *(const uint32_t*)(ph + 8);
            a[mt][3] = *(const uint32_t*)(ph + 8 * LDP + 8);
        }
#pragma unroll
        for (int nt = 0; nt < 8; nt++) {
            const unsigned short* pb = Bs + (ncol + nt * 8 + g) * LDP + k0 + tg * 2;
            uint32_t b0 = *(const uint32_t*)(pb);
            uint32_t b1 = *(const uint32_t*)(pb + 8);
#pragma unroll
            for (int mt = 0; mt < 2; mt++) {
                mma_f16(acc[mt][nt][0], acc[mt][nt][1], acc[mt][nt][2], acc[mt][nt][3],
                        a[mt][0], a[mt][1], a[mt][2], a[mt][3], b0, b1);
            }
        }
    }

#pragma unroll
    for (int mt = 0; mt < 2; mt++) {
        int r1 = m0 + mrow + mt * 16 + g;
        int r2 = r1 + 8;
        float d1 = (r1 < n) ? g_dis[r1] : 0.f;
        float d2 = (r2 < n) ? g_dis[r2] : 0.f;
#pragma unroll
        for (int nt = 0; nt < 8; nt++) {
            int col = ncol + nt * 8 + tg * 2;
            if (r1 < n)
                g_uh[(size_t)r1 * 64 + (col >> 1)] =
                    __floats2half2_rn(acc[mt][nt][0] * d1, acc[mt][nt][1] * d1);
            if (r2 < n)
                g_uh[(size_t)r2 * 64 + (col >> 1)] =
                    __floats2half2_rn(acc[mt][nt][2] * d2, acc[mt][nt][3] * d2);
        }
    }
}

// ---------------- fused CSR aggregation (fp16) + finalize (fp16 out) -----
__global__ void k_agg128(const float* __restrict__ bias, int n) {
    int gid = blockIdx.x * blockDim.x + threadIdx.x;
    int i = gid >> 5;
    int lane = threadIdx.x & 31;
    if (i >= n) return;
    int start = g_rowstart[i];
    int cnt   = g_deg[i];
    const uint2* U = (const uint2*)g_uh;

    uint2 su = U[(size_t)i * 32 + lane];
    float2 f0 = __half22float2(*(__half2*)&su.x);
    float2 f1 = __half22float2(*(__half2*)&su.y);
    float4 acc0 = make_float4(f0.x, f0.y, f1.x, f1.y);
    float4 acc1 = make_float4(0.f, 0.f, 0.f, 0.f);

    int j = 0;
    for (; j + 4 <= cnt; j += 4) {
        int s0 = g_col[start + j + 0];
        int s1 = g_col[start + j + 1];
        int s2 = g_col[start + j + 2];
        int s3 = g_col[start + j + 3];
        uint2 v0 = U[(size_t)s0 * 32 + lane];
        uint2 v1 = U[(size_t)s1 * 32 + lane];
        uint2 v2 = U[(size_t)s2 * 32 + lane];
        uint2 v3 = U[(size_t)s3 * 32 + lane];
        float2 a, b;
        a = __half22float2(*(__half2*)&v0.x); b = __half22float2(*(__half2*)&v0.y);
        acc0.x += a.x; acc0.y += a.y; acc0.z += b.x; acc0.w += b.y;
        a = __half22float2(*(__half2*)&v1.x); b = __half22float2(*(__half2*)&v1.y);
        acc1.x += a.x; acc1.y += a.y; acc1.z += b.x; acc1.w += b.y;
        a = __half22float2(*(__half2*)&v2.x); b = __half22float2(*(__half2*)&v2.y);
        acc0.x += a.x; acc0.y += a.y; acc0.z += b.x; acc0.w += b.y;
        a = __half22float2(*(__half2*)&v3.x); b = __half22float2(*(__half2*)&v3.y);
        acc1.x += a.x; acc1.y += a.y; acc1.z += b.x; acc1.w += b.y;
    }
    for (; j < cnt; j++) {
        int s = g_col[start + j];
        uint2 v = U[(size_t)s * 32 + lane];
        float2 a = __half22float2(*(__half2*)&v.x);
        float2 b = __half22float2(*(__half2*)&v.y);
        acc0.x += a.x; acc0.y += a.y; acc0.z += b.x; acc0.w += b.y;
    }
    float d = g_dis[i];
    float4 b = *(const float4*)(bias + lane * 4);
    float ox = fmaxf(d * (acc0.x + acc1.x) + b.x, 0.f);
    float oy = fmaxf(d * (acc0.y + acc1.y) + b.y, 0.f);
    float oz = fmaxf(d * (acc0.z + acc1.z) + b.z, 0.f);
    float ow = fmaxf(d * (acc0.w + acc1.w) + b.w, 0.f);
    uint2 p;
    *(__half2*)&p.x = __floats2half2_rn(ox, oy);
    *(__half2*)&p.y = __floats2half2_rn(oz, ow);
    ((uint2*)g_hh)[(size_t)i * 32 + lane] = p;
}

// ---------------- fused pool + output dense + invariant cleanup ----------
__global__ void k_pool_out(const int* __restrict__ batch, int n,
                           const float* __restrict__ W,
                           const float* __restrict__ b,
                           float* __restrict__ out) {
    __shared__ float pooled[128];
    __shared__ int seg[2];
    int g = blockIdx.x;
    int j = threadIdx.x;
    if (j < 2) {
        int v = g + j;
        int lo = 0, hi = n;
        while (lo < hi) {
            int m = (lo + hi) >> 1;
            if (batch[m] < v) lo = m + 1; else hi = m;
        }
        seg[j] = lo;
    }
    __syncthreads();
    int s = seg[0], e = seg[1];
    const __half* H = (const __half*)g_hh;
    float sum = 0.f;
    for (int i = s; i < e; i++) sum += __half2float(H[(size_t)i * 128 + j]);
    float inv = 1.f / fmaxf((float)(e - s), 1.f);
    pooled[j] = sum * inv;
    __syncthreads();
    float acc = b[j];
#pragma unroll 8
    for (int k = 0; k < 128; k++) acc += pooled[k] * W[k * 128 + j];
    out[g * 128 + j] = acc;
    int gid = g * 128 + j;
    for (int i = gid; i < n; i += NG * 128) g_deg[i] = 0;
    if (gid < 512) g_bsum[gid] = 0;
}

// ---------------- launch -------------------------------------------------
extern "C" void kernel_launch(void* const* d_in, const int* in_sizes, int n_in,
                              void* d_out, int out_size) {
    const float* x     = (const float*)d_in[0];
    const int*   ei    = (const int*)d_in[1];
    const int*   batch = (const int*)d_in[2];
    const float* W_d1 = (const float*)d_in[3];
    const float* b_d1 = (const float*)d_in[4];
    const float* W_g1 = (const float*)d_in[5];
    const float* b_g1 = (const float*)d_in[6];
    const float* W_g2 = (const float*)d_in[7];
    const float* b_g2 = (const float*)d_in[8];
    const float* W_g3 = (const float*)d_in[9];
    const float* b_g3 = (const float*)d_in[10];
    const float* W_d2 = (const float*)d_in[11];
    const float* b_d2 = (const float*)d_in[12];
    float* out = (float*)d_out;

    const int N = in_sizes[0] / 4;
    const int E = in_sizes[1] / 2;
    const int* src = ei;
    const int* dst = ei + E;
    const int T = 256;
    const int NB = (N + 255) / 256;        // 391
    const int NB128 = (N + 127) / 128;     // 782 (layer1 blocks)
    int edge_threads = (E + 3) / 4;
    if (edge_threads < N) edge_threads = N;
    const int EB4 = (edge_threads + T - 1) / T;

    const int GEMM_SMEM = 2 * 128 * LDP * 2;   // 69632 B
    cudaFuncSetAttribute(k_gemm_mma, cudaFuncAttributeMaxDynamicSharedMemorySize, GEMM_SMEM);

    k_front<<<EB4, T>>>(dst, E, W_g2, W_g3);
    k_scan<<<NB, 256>>>(N);
    k_fill_dense<<<EB4, T>>>(src, dst, E, x, W_d1, b_d1, N);
    k_layer1<<<NB128, 256>>>(W_g1, b_g1, N);

    const int gemm_blocks = (N + 127) / 128;
    const int agg_blocks  = (int)(((long long)N * 32 + T - 1) / T);

    k_gemm_mma<<<gemm_blocks, 256, GEMM_SMEM>>>(0, N);
    k_agg128<<<agg_blocks, T>>>(b_g2, N);
    k_gemm_mma<<<gemm_blocks, 256, GEMM_SMEM>>>(1, N);
    k_agg128<<<agg_blocks, T>>>(b_g3, N);
    k_pool_out<<<NG, 128>>>(batch, N, W_d2, b_d2, out);
}

// round 16
// speedup vs baseline: 1.0608x; 1.0608x over previous
#include <cuda_runtime.h>
#include <cuda_bf16.h>
#include <cuda_fp16.h>
#include <cstdint>

#define NN 100000
#define NE 1600000
#define NG 512
#define LDP 136   // padded smem row stride in fp16 elements (272 B)

// ---------------- scratch (device globals) -------------------------------
// Invariants at entry to each run (zero-init at load; k_pool_out restores):
//   g_deg[i] == 0, g_bsum[b] == 0
__device__ int    g_deg[NN];
__device__ float  g_dis[NN];
__device__ float4 g_u4[NN];
__device__ __align__(16) __half2 g_hh[NN * 64];   // fp16 node features
__device__ __align__(16) __half2 g_uh[NN * 64];   // fp16 projected features
__device__ int    g_rowstart[NN];
__device__ unsigned short g_rank[NE];             // within-row rank per edge
__device__ int    g_col[NE];
__device__ int    g_bsum[512];
__device__ __align__(16) unsigned short g_B[2][16384];

// ---------------- mma helper (f16 inputs, f32 accum) ---------------------
__device__ __forceinline__ void mma_f16(float& d0, float& d1, float& d2, float& d3,
                                        uint32_t a0, uint32_t a1, uint32_t a2, uint32_t a3,
                                        uint32_t b0, uint32_t b1) {
    asm volatile(
        "mma.sync.aligned.m16n8k16.row.col.f32.f16.f16.f32 "
        "{%0,%1,%2,%3}, {%4,%5,%6,%7}, {%8,%9}, {%0,%1,%2,%3};"
        : "+f"(d0), "+f"(d1), "+f"(d2), "+f"(d3)
        : "r"(a0), "r"(a1), "r"(a2), "r"(a3), "r"(b0), "r"(b1));
}

// ---------------- front: W prep + degree count + edge ranks --------------
__global__ void k_front(const int* __restrict__ dst, int E,
                        const float* __restrict__ W2, const float* __restrict__ W3) {
    int gid = blockIdx.x * blockDim.x + threadIdx.x;
    if (gid < 32768) {
        int which = gid >> 14;
        int idx = gid & 16383;
        int k  = idx >> 7;
        int nn = idx & 127;
        const float* W = which ? W3 : W2;
        g_B[which][nn * 128 + k] = __half_as_ushort(__float2half_rn(W[k * 128 + nn]));
    }
    int wid  = gid >> 5;
    int lane = gid & 31;
    int base = wid * 128 + lane;
    int d0 = -1, d1 = -1, d2 = -1, d3 = -1;
    if (base       < E) d0 = dst[base];
    if (base + 32  < E) d1 = dst[base + 32];
    if (base + 64  < E) d2 = dst[base + 64];
    if (base + 96  < E) d3 = dst[base + 96];
    int r0 = 0, r1 = 0, r2 = 0, r3 = 0;
    if (d0 >= 0) r0 = atomicAdd(&g_deg[d0], 1);
    if (d1 >= 0) r1 = atomicAdd(&g_deg[d1], 1);
    if (d2 >= 0) r2 = atomicAdd(&g_deg[d2], 1);
    if (d3 >= 0) r3 = atomicAdd(&g_deg[d3], 1);
    if (d0 >= 0) g_rank[base]      = (unsigned short)r0;
    if (d1 >= 0) g_rank[base + 32] = (unsigned short)r1;
    if (d2 >= 0) g_rank[base + 64] = (unsigned short)r2;
    if (d3 >= 0) g_rank[base + 96] = (unsigned short)r3;
}

// ---------------- merged scan (decoupled lookback) + dis -----------------
__global__ void k_scan(int n) {
    __shared__ int s[256];
    __shared__ int partials[256];
    int t = threadIdx.x;
    int bid = blockIdx.x;
    int i = bid * 256 + t;
    int raw = (i < n) ? g_deg[i] : 0;
    if (i < n) g_dis[i] = rsqrtf((float)(raw + 1));
    s[t] = raw;
    __syncthreads();
#pragma unroll
    for (int off = 1; off < 256; off <<= 1) {
        int x = (t >= off) ? s[t - off] : 0;
        __syncthreads();
        s[t] += x;
        __syncthreads();
    }
    if (t == 255) atomicExch(&g_bsum[bid], s[255] + 1);
    int partial = 0;
    for (int b = t; b < bid; b += 256) {
        int v;
        do { v = atomicAdd(&g_bsum[b], 0); } while (v == 0);
        partial += v - 1;
    }
    partials[t] = partial;
    __syncthreads();
#pragma unroll
    for (int off = 128; off > 0; off >>= 1) {
        if (t < off) partials[t] += partials[t + off];
        __syncthreads();
    }
    int base = partials[0];
    if (i < n) g_rowstart[i] = base + s[t] - raw;
}

// ---------------- fused: CSR fill (rank-based, no atomics) + dense1 ------
__global__ void k_fill_dense(const int* __restrict__ src,
                             const int* __restrict__ dst, int E,
                             const float* __restrict__ x,
                             const float* __restrict__ W,
                             const float* __restrict__ b, int n) {
    int gid = blockIdx.x * blockDim.x + threadIdx.x;
    int wid  = gid >> 5;
    int lane = gid & 31;
    int base = wid * 128 + lane;
    int d0 = -1, d1 = -1, d2 = -1, d3 = -1;
    int s0 = 0, s1 = 0, s2 = 0, s3 = 0;
    int r0 = 0, r1 = 0, r2 = 0, r3 = 0;
    if (base       < E) { d0 = dst[base];      s0 = src[base];      r0 = g_rank[base]; }
    if (base + 32  < E) { d1 = dst[base + 32]; s1 = src[base + 32]; r1 = g_rank[base + 32]; }
    if (base + 64  < E) { d2 = dst[base + 64]; s2 = src[base + 64]; r2 = g_rank[base + 64]; }
    if (base + 96  < E) { d3 = dst[base + 96]; s3 = src[base + 96]; r3 = g_rank[base + 96]; }
    int p0 = 0, p1 = 0, p2 = 0, p3 = 0;
    if (d0 >= 0) p0 = g_rowstart[d0] + r0;
    if (d1 >= 0) p1 = g_rowstart[d1] + r1;
    if (d2 >= 0) p2 = g_rowstart[d2] + r2;
    if (d3 >= 0) p3 = g_rowstart[d3] + r3;
    if (d0 >= 0) g_col[p0] = s0;
    if (d1 >= 0) g_col[p1] = s1;
    if (d2 >= 0) g_col[p2] = s2;
    if (d3 >= 0) g_col[p3] = s3;

    if (gid < n) {
        float4 xi = ((const float4*)x)[gid];
        float d = g_dis[gid];
        float4 o;
        o.x = fmaxf(b[0] + xi.x * W[0] + xi.y * W[4] + xi.z * W[8]  + xi.w * W[12], 0.f) * d;
        o.y = fmaxf(b[1] + xi.x * W[1] + xi.y * W[5] + xi.z * W[9]  + xi.w * W[13], 0.f) * d;
        o.z = fmaxf(b[2] + xi.x * W[2] + xi.y * W[6] + xi.z * W[10] + xi.w * W[14], 0.f) * d;
        o.w = fmaxf(b[3] + xi.x * W[3] + xi.y * W[7] + xi.z * W[11] + xi.w * W[15], 0.f) * d;
        g_u4[gid] = o;
    }
}

// ---------------- layer1 (R14 form): thread-per-node agg + warp proj -----
// grid: 391 blocks x 256 threads; block handles 256 nodes.
__global__ void k_layer1(const float* __restrict__ Wg1,
                         const float* __restrict__ bg1, int n) {
    __shared__ float4 sagg[256];
    int t = threadIdx.x;
    int i = blockIdx.x * 256 + t;

    if (i < n) {
        int start = g_rowstart[i];
        int cnt   = g_deg[i];
        float4 a0 = g_u4[i];   // self-loop
        float4 a1 = make_float4(0.f, 0.f, 0.f, 0.f);
        int j = 0;
        for (; j + 4 <= cnt; j += 4) {
            int c0 = g_col[start + j + 0];
            int c1 = g_col[start + j + 1];
            int c2 = g_col[start + j + 2];
            int c3 = g_col[start + j + 3];
            float4 v0 = g_u4[c0];
            float4 v1 = g_u4[c1];
            float4 v2 = g_u4[c2];
            float4 v3 = g_u4[c3];
            a0.x += v0.x; a0.y += v0.y; a0.z += v0.z; a0.w += v0.w;
            a1.x += v1.x; a1.y += v1.y; a1.z += v1.z; a1.w += v1.w;
            a0.x += v2.x; a0.y += v2.y; a0.z += v2.z; a0.w += v2.w;
            a1.x += v3.x; a1.y += v3.y; a1.z += v3.z; a1.w += v3.w;
        }
        for (; j < cnt; j++) {
            float4 v = g_u4[g_col[start + j]];
            a0.x += v.x; a0.y += v.y; a0.z += v.z; a0.w += v.w;
        }
        float d = g_dis[i];
        sagg[t] = make_float4(d * (a0.x + a1.x), d * (a0.y + a1.y),
                              d * (a0.z + a1.z), d * (a0.w + a1.w));
    } else {
        sagg[t] = make_float4(0.f, 0.f, 0.f, 0.f);
    }
    __syncthreads();

    int w = t >> 5;
    int lane = t & 31;
    int c = lane * 4;
    float4 w0 = *(const float4*)(Wg1 + 0 * 128 + c);
    float4 w1 = *(const float4*)(Wg1 + 1 * 128 + c);
    float4 w2 = *(const float4*)(Wg1 + 2 * 128 + c);
    float4 w3 = *(const float4*)(Wg1 + 3 * 128 + c);
    float4 bb = *(const float4*)(bg1 + c);
    int nd0 = w * 32;
#pragma unroll 4
    for (int k = 0; k < 32; k++) {
        int gi = blockIdx.x * 256 + nd0 + k;
        if (gi >= n) break;
        float4 a = sagg[nd0 + k];
        float ox = fmaxf(bb.x + a.x * w0.x + a.y * w1.x + a.z * w2.x + a.w * w3.x, 0.f);
        float oy = fmaxf(bb.y + a.x * w0.y + a.y * w1.y + a.z * w2.y + a.w * w3.y, 0.f);
        float oz = fmaxf(bb.z + a.x * w0.z + a.y * w1.z + a.z * w2.z + a.w * w3.z, 0.f);
        float ow = fmaxf(bb.w + a.x * w0.w + a.y * w1.w + a.z * w2.w + a.w * w3.w, 0.f);
        uint2 p;
        *(__half2*)&p.x = __floats2half2_rn(ox, oy);
        *(__half2*)&p.y = __floats2half2_rn(oz, ow);
        ((uint2*)g_hh)[(size_t)gi * 32 + lane] = p;
    }
}

// ---------------- mma.sync GEMM: u16 = fp16(dis * (h16 @ W)) -------------
__global__ void __launch_bounds__(256, 2)
k_gemm_mma(int which, int n) {
    extern __shared__ __align__(16) unsigned short sm[];
    unsigned short* As = sm;
    unsigned short* Bs = sm + 128 * LDP;

    const int tid = threadIdx.x;
    const int m0 = blockIdx.x * 128;

    for (int idx = tid; idx < 2048; idx += 256) {
        int row = idx >> 4;
        int q   = idx & 15;
        int gr = m0 + row;
        if (gr >= n) gr = n - 1;
        uint4 v = ((const uint4*)g_hh)[(size_t)gr * 16 + q];
        *(uint4*)(As + row * LDP + q * 8) = v;
    }
    {
        const uint4* bsrc = (const uint4*)g_B[which];
        for (int i = tid; i < 2048; i += 256) {
            int r = i >> 4;
            int q = i & 15;
            *(uint4*)(Bs + r * LDP + q * 8) = bsrc[i];
        }
    }
    __syncthreads();

    const int w    = tid >> 5;
    const int lane = tid & 31;
    const int mrow = (w >> 1) * 32;
    const int ncol = (w & 1) * 64;
    const int g    = lane >> 2;
    const int tg   = lane & 3;

    float acc[2][8][4];
#pragma unroll
    for (int mt = 0; mt < 2; mt++)
#pragma unroll
        for (int nt = 0; nt < 8; nt++)
#pragma unroll
            for (int c = 0; c < 4; c++) acc[mt][nt][c] = 0.f;

    for (int k0 = 0; k0 < 128; k0 += 16) {
        uint32_t a[2][4];
#pragma unroll
        for (int mt = 0; mt < 2; mt++) {
            const unsigned short* ph = As + (mrow + mt * 16 + g) * LDP + k0 + tg * 2;
            a[mt][0] = *(const uint32_t*)(ph);
            a[mt][1] = *(const uint32_t*)(ph + 8 * LDP);
            a[mt][2] = *(const uint32_t*)(ph + 8);
            a[mt][3] = *(const uint32_t*)(ph + 8 * LDP + 8);
        }
#pragma unroll
        for (int nt = 0; nt < 8; nt++) {
            const unsigned short* pb = Bs + (ncol + nt * 8 + g) * LDP + k0 + tg * 2;
            uint32_t b0 = *(const uint32_t*)(pb);
            uint32_t b1 = *(const uint32_t*)(pb + 8);
#pragma unroll
            for (int mt = 0; mt < 2; mt++) {
                mma_f16(acc[mt][nt][0], acc[mt][nt][1], acc[mt][nt][2], acc[mt][nt][3],
                        a[mt][0], a[mt][1], a[mt][2], a[mt][3], b0, b1);
            }
        }
    }

#pragma unroll
    for (int mt = 0; mt < 2; mt++) {
        int r1 = m0 + mrow + mt * 16 + g;
        int r2 = r1 + 8;
        float d1 = (r1 < n) ? g_dis[r1] : 0.f;
        float d2 = (r2 < n) ? g_dis[r2] : 0.f;
#pragma unroll
        for (int nt = 0; nt < 8; nt++) {
            int col = ncol + nt * 8 + tg * 2;
            if (r1 < n)
                g_uh[(size_t)r1 * 64 + (col >> 1)] =
                    __floats2half2_rn(acc[mt][nt][0] * d1, acc[mt][nt][1] * d1);
            if (r2 < n)
                g_uh[(size_t)r2 * 64 + (col >> 1)] =
                    __floats2half2_rn(acc[mt][nt][2] * d2, acc[mt][nt][3] * d2);
        }
    }
}

// ---------------- fused CSR aggregation (fp16, 8-deep MLP) + finalize ----
__global__ void k_agg128(const float* __restrict__ bias, int n) {
    int gid = blockIdx.x * blockDim.x + threadIdx.x;
    int i = gid >> 5;
    int lane = threadIdx.x & 31;
    if (i >= n) return;
    int start = g_rowstart[i];
    int cnt   = g_deg[i];
    const uint2* U = (const uint2*)g_uh;

    uint2 su = U[(size_t)i * 32 + lane];
    float2 f0 = __half22float2(*(__half2*)&su.x);
    float2 f1 = __half22float2(*(__half2*)&su.y);
    float4 acc0 = make_float4(f0.x, f0.y, f1.x, f1.y);
    float4 acc1 = make_float4(0.f, 0.f, 0.f, 0.f);

    int j = 0;
    // 8 independent gathers in flight
    for (; j + 8 <= cnt; j += 8) {
        int c0 = g_col[start + j + 0];
        int c1 = g_col[start + j + 1];
        int c2 = g_col[start + j + 2];
        int c3 = g_col[start + j + 3];
        int c4 = g_col[start + j + 4];
        int c5 = g_col[start + j + 5];
        int c6 = g_col[start + j + 6];
        int c7 = g_col[start + j + 7];
        uint2 v0 = U[(size_t)c0 * 32 + lane];
        uint2 v1 = U[(size_t)c1 * 32 + lane];
        uint2 v2 = U[(size_t)c2 * 32 + lane];
        uint2 v3 = U[(size_t)c3 * 32 + lane];
        uint2 v4 = U[(size_t)c4 * 32 + lane];
        uint2 v5 = U[(size_t)c5 * 32 + lane];
        uint2 v6 = U[(size_t)c6 * 32 + lane];
        uint2 v7 = U[(size_t)c7 * 32 + lane];
        float2 a, b;
        a = __half22float2(*(__half2*)&v0.x); b = __half22float2(*(__half2*)&v0.y);
        acc0.x += a.x; acc0.y += a.y; acc0.z += b.x; acc0.w += b.y;
        a = __half22float2(*(__half2*)&v1.x); b = __half22float2(*(__half2*)&v1.y);
        acc1.x += a.x; acc1.y += a.y; acc1.z += b.x; acc1.w += b.y;
        a = __half22float2(*(__half2*)&v2.x); b = __half22float2(*(__half2*)&v2.y);
        acc0.x += a.x; acc0.y += a.y; acc0.z += b.x; acc0.w += b.y;
        a = __half22float2(*(__half2*)&v3.x); b = __half22float2(*(__half2*)&v3.y);
        acc1.x += a.x; acc1.y += a.y; acc1.z += b.x; acc1.w += b.y;
        a = __half22float2(*(__half2*)&v4.x); b = __half22float2(*(__half2*)&v4.y);
        acc0.x += a.x; acc0.y += a.y; acc0.z += b.x; acc0.w += b.y;
        a = __half22float2(*(__half2*)&v5.x); b = __half22float2(*(__half2*)&v5.y);
        acc1.x += a.x; acc1.y += a.y; acc1.z += b.x; acc1.w += b.y;
        a = __half22float2(*(__half2*)&v6.x); b = __half22float2(*(__half2*)&v6.y);
        acc0.x += a.x; acc0.y += a.y; acc0.z += b.x; acc0.w += b.y;
        a = __half22float2(*(__half2*)&v7.x); b = __half22float2(*(__half2*)&v7.y);
        acc1.x += a.x; acc1.y += a.y; acc1.z += b.x; acc1.w += b.y;
    }
    for (; j + 4 <= cnt; j += 4) {
        int c0 = g_col[start + j + 0];
        int c1 = g_col[start + j + 1];
        int c2 = g_col[start + j + 2];
        int c3 = g_col[start + j + 3];
        uint2 v0 = U[(size_t)c0 * 32 + lane];
        uint2 v1 = U[(size_t)c1 * 32 + lane];
        uint2 v2 = U[(size_t)c2 * 32 + lane];
        uint2 v3 = U[(size_t)c3 * 32 + lane];
        float2 a, b;
        a = __half22float2(*(__half2*)&v0.x); b = __half22float2(*(__half2*)&v0.y);
        acc0.x += a.x; acc0.y += a.y; acc0.z += b.x; acc0.w += b.y;
        a = __half22float2(*(__half2*)&v1.x); b = __half22float2(*(__half2*)&v1.y);
        acc1.x += a.x; acc1.y += a.y; acc1.z += b.x; acc1.w += b.y;
        a = __half22float2(*(__half2*)&v2.x); b = __half22float2(*(__half2*)&v2.y);
        acc0.x += a.x; acc0.y += a.y; acc0.z += b.x; acc0.w += b.y;
        a = __half22float2(*(__half2*)&v3.x); b = __half22float2(*(__half2*)&v3.y);
        acc1.x += a.x; acc1.y += a.y; acc1.z += b.x; acc1.w += b.y;
    }
    for (; j < cnt; j++) {
        int s = g_col[start + j];
        uint2 v = U[(size_t)s * 32 + lane];
        float2 a = __half22float2(*(__half2*)&v.x);
        float2 b = __half22float2(*(__half2*)&v.y);
        acc0.x += a.x; acc0.y += a.y; acc0.z += b.x; acc0.w += b.y;
    }
    float d = g_dis[i];
    float4 b = *(const float4*)(bias + lane * 4);
    float ox = fmaxf(d * (acc0.x + acc1.x) + b.x, 0.f);
    float oy = fmaxf(d * (acc0.y + acc1.y) + b.y, 0.f);
    float oz = fmaxf(d * (acc0.z + acc1.z) + b.z, 0.f);
    float ow = fmaxf(d * (acc0.w + acc1.w) + b.w, 0.f);
    uint2 p;
    *(__half2*)&p.x = __floats2half2_rn(ox, oy);
    *(__half2*)&p.y = __floats2half2_rn(oz, ow);
    ((uint2*)g_hh)[(size_t)i * 32 + lane] = p;
}

// ---------------- fused pool + output dense + invariant cleanup ----------
__global__ void k_pool_out(const int* __restrict__ batch, int n,
                           const float* __restrict__ W,
                           const float* __restrict__ b,
                           float* __restrict__ out) {
    __shared__ float pooled[128];
    __shared__ int seg[2];
    int g = blockIdx.x;
    int j = threadIdx.x;
    if (j < 2) {
        int v = g + j;
        int lo = 0, hi = n;
        while (lo < hi) {
            int m = (lo + hi) >> 1;
            if (batch[m] < v) lo = m + 1; else hi = m;
        }
        seg[j] = lo;
    }
    __syncthreads();
    int s = seg[0], e = seg[1];
    const __half* H = (const __half*)g_hh;
    float sum = 0.f;
    for (int i = s; i < e; i++) sum += __half2float(H[(size_t)i * 128 + j]);
    float inv = 1.f / fmaxf((float)(e - s), 1.f);
    pooled[j] = sum * inv;
    __syncthreads();
    float acc = b[j];
#pragma unroll 8
    for (int k = 0; k < 128; k++) acc += pooled[k] * W[k * 128 + j];
    out[g * 128 + j] = acc;
    int gid = g * 128 + j;
    for (int i = gid; i < n; i += NG * 128) g_deg[i] = 0;
    if (gid < 512) g_bsum[gid] = 0;
}

// ---------------- launch -------------------------------------------------
extern "C" void kernel_launch(void* const* d_in, const int* in_sizes, int n_in,
                              void* d_out, int out_size) {
    const float* x     = (const float*)d_in[0];
    const int*   ei    = (const int*)d_in[1];
    const int*   batch = (const int*)d_in[2];
    const float* W_d1 = (const float*)d_in[3];
    const float* b_d1 = (const float*)d_in[4];
    const float* W_g1 = (const float*)d_in[5];
    const float* b_g1 = (const float*)d_in[6];
    const float* W_g2 = (const float*)d_in[7];
    const float* b_g2 = (const float*)d_in[8];
    const float* W_g3 = (const float*)d_in[9];
    const float* b_g3 = (const float*)d_in[10];
    const float* W_d2 = (const float*)d_in[11];
    const float* b_d2 = (const float*)d_in[12];
    float* out = (float*)d_out;

    const int N = in_sizes[0] / 4;
    const int E = in_sizes[1] / 2;
    const int* src = ei;
    const int* dst = ei + E;
    const int T = 256;
    const int NB = (N + 255) / 256;        // 391
    int edge_threads = (E + 3) / 4;
    if (edge_threads < N) edge_threads = N;
    const int EB4 = (edge_threads + T - 1) / T;

    const int GEMM_SMEM = 2 * 128 * LDP * 2;   // 69632 B
    cudaFuncSetAttribute(k_gemm_mma, cudaFuncAttributeMaxDynamicSharedMemorySize, GEMM_SMEM);

    k_front<<<EB4, T>>>(dst, E, W_g2, W_g3);
    k_scan<<<NB, 256>>>(N);
    k_fill_dense<<<EB4, T>>>(src, dst, E, x, W_d1, b_d1, N);
    k_layer1<<<NB, 256>>>(W_g1, b_g1, N);

    const int gemm_blocks = (N + 127) / 128;
    const int agg_blocks  = (int)(((long long)N * 32 + T - 1) / T);

    k_gemm_mma<<<gemm_blocks, 256, GEMM_SMEM>>>(0, N);
    k_agg128<<<agg_blocks, T>>>(b_g2, N);
    k_gemm_mma<<<gemm_blocks, 256, GEMM_SMEM>>>(1, N);
    k_agg128<<<agg_blocks, T>>>(b_g3, N);
    k_pool_out<<<NG, 128>>>(batch, N, W_d2, b_d2, out);
}